// round 15
// baseline (speedup 1.0000x reference)
#include <cuda_runtime.h>
#include <cuda_bf16.h>
#include <cstdint>
#include <cstddef>

typedef unsigned long long u64;
typedef unsigned int u32;
typedef unsigned short u16;

// ---------------------------------------------------------------------------
// Scratch buffers (device globals; no allocations anywhere).
// B1..B6 hold packed bf16(hi,lo) u32 per element; B7 holds fp32.
// ---------------------------------------------------------------------------
static constexpr size_t S_B1 = 64ull * 96 * 4092;
static constexpr size_t S_B2 = 64ull * 96 * 2044;
static constexpr size_t S_B3 = 64ull * 96 * 1020;
static constexpr size_t S_B4 = 64ull * 96 * 508;
static constexpr size_t S_B5 = 64ull * 96 * 125;
static constexpr size_t S_B6 = 64ull * 96 * 29;
static constexpr size_t S_B7 = 64ull * 128 * 14;

static constexpr size_t OFF_B1 = 0;
static constexpr size_t OFF_B2 = OFF_B1 + S_B1;
static constexpr size_t OFF_B3 = OFF_B2 + S_B2;
static constexpr size_t OFF_B4 = OFF_B3 + S_B3;
static constexpr size_t OFF_B5 = OFF_B4 + S_B4;
static constexpr size_t OFF_B6 = OFF_B5 + S_B5;
static constexpr size_t OFF_B7 = OFF_B6 + S_B6;
static constexpr size_t SCRATCH_TOTAL = OFF_B7 + S_B7;

__device__ u32 g_scratch[SCRATCH_TOTAL];

// pre-split weights (bf16 hi/lo), layout [NCH][O][64] with chunk = CPC
// channels x K taps (c = li*K + k), zero-padded.
static constexpr int W1H = 0,      W1L = 43008;    // O=96  NCH=7 (CPC=6, K=10)
static constexpr int W2H = 86016,  W2L = 135168;   // O=96  NCH=8 (CPC=12, K=5)
static constexpr int W3H = 184320, W3L = 233472;
static constexpr int W4H = 282624, W4L = 331776;
static constexpr int W5H = 380928, W5L = 430080;
static constexpr int W6H = 479232, W6L = 528384;
static constexpr int W7H = 577536, W7L = 618496;   // O=128 NCH=5 (CPC=21, K=3)
__device__ __align__(256) u16 g_wsplit[659456];

// ---------------------------------------------------------------------------
// PTX helpers (baseline ISA only — compiles at compute_103)
// ---------------------------------------------------------------------------
__device__ __forceinline__ void ldsm_x4(u32* r, u32 addr) {
    asm volatile("ldmatrix.sync.aligned.m8n8.x4.shared.b16 {%0,%1,%2,%3}, [%4];"
                 : "=r"(r[0]), "=r"(r[1]), "=r"(r[2]), "=r"(r[3]) : "r"(addr));
}
__device__ __forceinline__ void mma_bf16(float* d, const u32* a, const u32* b) {
    asm volatile(
        "mma.sync.aligned.m16n8k16.row.col.f32.bf16.bf16.f32 "
        "{%0,%1,%2,%3}, {%4,%5,%6,%7}, {%8,%9}, {%0,%1,%2,%3};"
        : "+f"(d[0]), "+f"(d[1]), "+f"(d[2]), "+f"(d[3])
        : "r"(a[0]), "r"(a[1]), "r"(a[2]), "r"(a[3]), "r"(b[0]), "r"(b[1]));
}
#define STS128(addr, a, b, c, d) \
    asm volatile("st.shared.v4.b32 [%0], {%1, %2, %3, %4};" \
                 :: "r"((u32)(addr)), "r"(a), "r"(b), "r"(c), "r"(d) : "memory")

__device__ __forceinline__ u32 smem_u32(const void* p) {
    u32 a;
    asm("{ .reg .u64 t; cvta.to.shared.u64 t, %1; cvt.u32.u64 %0, t; }"
        : "=r"(a) : "l"(p));
    return a;
}

// fp32 -> packed (bf16 hi | bf16 lo << 16), value ~= hi + lo
__device__ __forceinline__ u32 split1(float v) {
    __nv_bfloat16 h = __float2bfloat16_rn(v);
    __nv_bfloat16 l = __float2bfloat16_rn(v - __bfloat162float(h));
    return (u32)__bfloat16_as_ushort(h) | ((u32)__bfloat16_as_ushort(l) << 16);
}
__device__ __forceinline__ float unsplit1(u32 p) {
    return __bfloat162float(__ushort_as_bfloat16((u16)(p & 0xFFFF))) +
           __bfloat162float(__ushort_as_bfloat16((u16)(p >> 16)));
}

// layout constants (host + device agree). M tile = 128; x fully resident.
__host__ __device__ constexpr int cx_cpc(int K)   { return 64 / K; }
__host__ __device__ constexpr int cx_nch(int I, int K) {
    return (I + cx_cpc(K) - 1) / cx_cpc(K);
}
__host__ __device__ constexpr int cx_uspan(int K) { return 256 + K; }
__host__ __device__ constexpr int cx_xrows(int I, int K) {
    return cx_nch(I, K) * cx_cpc(K) + 1;      // +1 zero pad row
}
__host__ __device__ constexpr int cx_aoff(int I, int K) {
    return (512 + cx_xrows(I, K) * cx_uspan(K) * 4 + 15) & ~15;
}
__host__ __device__ constexpr int cx_boff(int I, int K) {
    return cx_aoff(I, K) + 4 * 128 * 144;     // A: 2 bufs x (hi,lo) x 18432B
}
__host__ __device__ constexpr int cx_smem(int I, int K, int O) {
    int total = cx_boff(I, K) + 2 * O * 144;  // B single buffer (hi,lo)
    int dmin = 512 + 128 * (O + 1) * 4;       // epilogue overlay
    return total > dmin ? total : dmin;
}

// ---------------------------------------------------------------------------
// Weight pre-split into chunked layout [NCH][O][64], c = li*K + k
// ---------------------------------------------------------------------------
__global__ void presplit_w_kernel(
    const float* __restrict__ w1, const float* __restrict__ w2,
    const float* __restrict__ w3, const float* __restrict__ w4,
    const float* __restrict__ w5, const float* __restrict__ w6,
    const float* __restrict__ w7) {
    int n = blockIdx.x * blockDim.x + threadIdx.x;
    const float* w; int I, O, K; u16 *hi, *lo; int idx;
    if      (n < 43008)  { w = w1; I = 40; O = 96;  K = 10; hi = g_wsplit + W1H; lo = g_wsplit + W1L; idx = n; }
    else if (n < 92160)  { w = w2; I = 96; O = 96;  K = 5;  hi = g_wsplit + W2H; lo = g_wsplit + W2L; idx = n - 43008; }
    else if (n < 141312) { w = w3; I = 96; O = 96;  K = 5;  hi = g_wsplit + W3H; lo = g_wsplit + W3L; idx = n - 92160; }
    else if (n < 190464) { w = w4; I = 96; O = 96;  K = 5;  hi = g_wsplit + W4H; lo = g_wsplit + W4L; idx = n - 141312; }
    else if (n < 239616) { w = w5; I = 96; O = 96;  K = 5;  hi = g_wsplit + W5H; lo = g_wsplit + W5L; idx = n - 190464; }
    else if (n < 288768) { w = w6; I = 96; O = 96;  K = 5;  hi = g_wsplit + W6H; lo = g_wsplit + W6L; idx = n - 239616; }
    else if (n < 329728) { w = w7; I = 96; O = 128; K = 3;  hi = g_wsplit + W7H; lo = g_wsplit + W7L; idx = n - 288768; }
    else return;
    int CPC = 64 / K;
    int c  = idx & 63;
    int o  = (idx >> 6) % O;
    int ch = idx / (64 * O);
    int li = c / K;
    int k  = c - li * K;
    int i  = ch * CPC + li;
    float v = (li < CPC && i < I) ? w[(o * I + i) * K + k] : 0.f;
    u32 p = split1(v);
    hi[idx] = (u16)(p & 0xFFFF);
    lo[idx] = (u16)(p >> 16);
}

// ---------------------------------------------------------------------------
// Implicit-GEMM conv via HMMA, bf16 split, 3 passes. CTA: M tile = 128,
// 256 threads = 8 warps = 4 m-warps (m32) x 2 n-warps (n = O/2).
// x fully resident; A double-buffered (stage of ch+1 overlaps compute of ch);
// B single smem buffer, double-buffered through REGISTERS: per chunk,
// stsB(pB=B(ch)) THEN ldgB(ch+1) (read-before-overwrite, per-thread order),
// the LDG landing under compute(ch). 1 CTA/SM.
// IN_MODE: 0 = fp32 input, 1 = packed u32 input, 2 = packed + avgpool2 + relu
// ---------------------------------------------------------------------------
template <int I, int O, int K, bool RELU, int IN_MODE, bool OUT_PACKED>
__global__ __launch_bounds__(256, 1)
void conv_hmma_kernel(const void* __restrict__ xv,
                      const u16* __restrict__ whi, const u16* __restrict__ wlo,
                      const float* __restrict__ bias, void* __restrict__ yv,
                      int Tin, int TinRaw, int Tconv) {
    constexpr int CPC   = cx_cpc(K);
    constexpr int NCH   = cx_nch(I, K);
    constexpr int USPAN = cx_uspan(K);
    constexpr int XP    = USPAN;             // exact pitch (u32 elements)
    constexpr int XROWS = cx_xrows(I, K);
    constexpr int A_OFF = cx_aoff(I, K);
    constexpr int B_OFF = cx_boff(I, K);
    constexpr int APB   = 128 * 144;         // one A plane (hi or lo)
    constexpr int BPB   = O * 144;           // one B plane
    constexpr int NP    = O / 32;            // n8-tile pairs per n-warp
    constexpr int DP    = O + 1;
    constexpr int NSEG  = O / 32;            // 16B segs per thread per plane

    extern __shared__ char smem[];
    const u32 sm = smem_u32(smem);
    float* bias_sh = reinterpret_cast<float*>(smem);
    u32*   xsp     = reinterpret_cast<u32*>(smem + 512);   // [XROWS][XP]

    const int b    = blockIdx.y;
    const int t0   = blockIdx.x * 128;
    const int tid  = threadIdx.x;
    const int wid  = tid >> 5;
    const int lane = tid & 31;
    const int mw   = wid & 3;                // 4 m-warps (m32 each)
    const int nw   = wid >> 2;               // 2 n-warps (n = O/2)
    const int tA   = tid >> 3;               // gather: time row (0..31)
    const int gA   = tid & 7;                // gather: 8-col group

    if (tid < O) bias_sh[tid] = bias[tid];

    // ---- B register prefetch machinery --------------------------------------
    uint4 pB[2 * NSEG];
    auto ldgB = [&](int ch) {
        const uint4* sH = reinterpret_cast<const uint4*>(whi + (size_t)ch * O * 64);
        const uint4* sL = reinterpret_cast<const uint4*>(wlo + (size_t)ch * O * 64);
#pragma unroll
        for (int j = 0; j < NSEG; j++) {
            pB[j]        = sH[tid + 256 * j];
            pB[NSEG + j] = sL[tid + 256 * j];
        }
    };
    auto stsB = [&]() {
#pragma unroll
        for (int j = 0; j < NSEG; j++) {
            int s = tid + 256 * j;
            u32 addr = sm + B_OFF + (u32)((s >> 3) * 144 + (s & 7) * 16);
            STS128(addr, pB[j].x, pB[j].y, pB[j].z, pB[j].w);
            STS128(addr + BPB, pB[NSEG + j].x, pB[NSEG + j].y,
                   pB[NSEG + j].z, pB[NSEG + j].w);
        }
    };

    ldgB(0);   // fire first B load; latency hidden under x staging

    // ---- stage full x slice once (packed u32), zero pad rows ----------------
    // Vectorized path requires 16B-aligned row bases: (Tin & 3) == 0.
    if (IN_MODE == 1 && (Tin & 3) == 0) {
        const u32* xu = (const u32*)xv;
        constexpr int UV4 = (USPAN + 3) / 4;
        for (int v = tid; v < I * UV4; v += 256) {
            int i = v / UV4;
            int u = (v - i * UV4) * 4;
            int tg = 2 * t0 + u;
            const u32* src = xu + ((size_t)b * I + i) * Tin;
            if (u + 4 <= USPAN && tg + 4 <= Tin) {
                uint4 q = *reinterpret_cast<const uint4*>(src + tg);
                u32* d = xsp + i * XP + u;
                d[0] = q.x; d[1] = q.y; d[2] = q.z; d[3] = q.w;
            } else {
#pragma unroll
                for (int e = 0; e < 4; e++) {
                    if (u + e < USPAN)
                        xsp[i * XP + u + e] = (tg + e < Tin) ? src[tg + e] : 0u;
                }
            }
        }
    } else {
        for (int n = tid; n < I * USPAN; n += 256) {
            int i = n / USPAN;
            int u = n - i * USPAN;
            int tg = 2 * t0 + u;
            u32 pv = 0;
            if (tg < Tin) {
                if (IN_MODE == 0) {
                    const float* xf = (const float*)xv;
                    pv = split1(xf[((size_t)b * I + i) * Tin + tg]);
                } else if (IN_MODE == 1) {
                    const u32* xu = (const u32*)xv;
                    pv = xu[((size_t)b * I + i) * Tin + tg];
                } else {
                    const u32* xu = (const u32*)xv;
                    const u32* row = xu + ((size_t)b * I + i) * TinRaw + 2 * tg;
                    float f = 0.5f * (unsplit1(row[0]) + unsplit1(row[1]));
                    pv = split1(fmaxf(f, 0.f));
                }
            }
            xsp[i * XP + u] = pv;
        }
    }
    for (int n = tid; n < (XROWS - I) * XP; n += 256) xsp[I * XP + n] = 0;

    // chunk-invariant gather offsets (K constexpr -> no IDIV)
    int goff[8];
#pragma unroll
    for (int e = 0; e < 8; e++) {
        int cg = gA * 8 + e;
        int li = cg / K;
        int k  = cg - li * K;
        goff[e] = li * XP + k;
    }

    // A staging: write chunk ch into buffer buf (4 row-blocks of 32 per thread)
    auto stage_A = [&](int ch, int buf) {
        const u32* xb = xsp + ch * (CPC * XP);
        const u32 aH = sm + A_OFF + (u32)(buf * 2) * APB;
        const u32 aL = aH + APB;
#pragma unroll
        for (int uu = 0; uu < 4; uu++) {
            int t = tA + 32 * uu;
            u32 s[8];
#pragma unroll
            for (int e = 0; e < 8; e++) s[e] = xb[goff[e] + 2 * t];
            u32 ph[4], pl[4];
#pragma unroll
            for (int e2 = 0; e2 < 4; e2++) {
                ph[e2] = __byte_perm(s[2 * e2], s[2 * e2 + 1], 0x5410);
                pl[e2] = __byte_perm(s[2 * e2], s[2 * e2 + 1], 0x7632);
            }
            u32 off = (u32)(t * 144 + gA * 16);
            STS128(aH + off, ph[0], ph[1], ph[2], ph[3]);
            STS128(aL + off, pl[0], pl[1], pl[2], pl[3]);
        }
    };

    // ldsm lane offsets (m-warp rows 32*mw..32*mw+31; two m16 tiles)
    const u32 a_loff = (u32)((32 * mw + (lane & 7) + ((lane >> 3) & 1) * 8) * 144
                             + (lane >> 4) * 16);
    const u32 b_loff = (u32)((nw * (O / 2) + ((lane >> 4) << 3) + (lane & 7)) * 144
                             + ((lane >> 3) & 1) * 16);

    float acc[2][2 * NP][4];
#pragma unroll
    for (int mt = 0; mt < 2; mt++)
#pragma unroll
        for (int nt = 0; nt < 2 * NP; nt++)
#pragma unroll
            for (int q = 0; q < 4; q++) acc[mt][nt][q] = 0.f;

    __syncthreads();          // xsp ready (immutable from here on)
    stage_A(0, 0);            // A(0) into buf0  (pB still holds B(0))

    const u32 bh_b = sm + B_OFF + b_loff;
    const u32 bl_b = bh_b + BPB;

    for (int ch = 0; ch < NCH; ch++) {
        const int bf = ch & 1;
        __syncthreads();                    // compute(ch-1) done; A STS retired
        stsB();                             // replay B(ch) regs -> smem
        if (ch + 1 < NCH) ldgB(ch + 1);     // AFTER stsB: safe overwrite of pB;
                                            // LDG lands under compute(ch)
        __syncthreads();                    // A(ch)+B(ch) visible to all

        if (ch + 1 < NCH) stage_A(ch + 1, 1 - bf);  // overlaps compute below

        const u32 ah_b = sm + A_OFF + (u32)(bf * 2) * APB + a_loff;
        const u32 al_b = ah_b + APB;
#pragma unroll
        for (int ks = 0; ks < 4; ks++) {
            u32 ahi[2][4], alo[2][4];
#pragma unroll
            for (int mt = 0; mt < 2; mt++) {
                ldsm_x4(ahi[mt], ah_b + (u32)(mt * 16 * 144) + ks * 32);
                ldsm_x4(alo[mt], al_b + (u32)(mt * 16 * 144) + ks * 32);
            }
            u32 bhi[NP][4], blo[NP][4];
#pragma unroll
            for (int p = 0; p < NP; p++) {
                ldsm_x4(bhi[p], bh_b + (u32)(p * 16 * 144) + ks * 32);
                ldsm_x4(blo[p], bl_b + (u32)(p * 16 * 144) + ks * 32);
            }
#pragma unroll
            for (int p = 0; p < NP; p++)
#pragma unroll
                for (int mt = 0; mt < 2; mt++) {
                    mma_bf16(acc[mt][2 * p],     ahi[mt], bhi[p]);
                    mma_bf16(acc[mt][2 * p + 1], ahi[mt], bhi[p] + 2);
                }
#pragma unroll
            for (int p = 0; p < NP; p++)
#pragma unroll
                for (int mt = 0; mt < 2; mt++) {
                    mma_bf16(acc[mt][2 * p],     ahi[mt], blo[p]);
                    mma_bf16(acc[mt][2 * p + 1], ahi[mt], blo[p] + 2);
                }
#pragma unroll
            for (int p = 0; p < NP; p++)
#pragma unroll
                for (int mt = 0; mt < 2; mt++) {
                    mma_bf16(acc[mt][2 * p],     alo[mt], bhi[p]);
                    mma_bf16(acc[mt][2 * p + 1], alo[mt], bhi[p] + 2);
                }
        }
    }

    // ---- epilogue: frags -> smem (pitch DP) -> coalesced gmem ---------------
    __syncthreads();
    float* Dt = reinterpret_cast<float*>(smem + 512);
    const int g = lane >> 2, c = lane & 3;
#pragma unroll
    for (int mt = 0; mt < 2; mt++) {
        const int r0 = 32 * mw + 16 * mt + g;
#pragma unroll
        for (int nt = 0; nt < 2 * NP; nt++) {
            int n0 = nw * (O / 2) + nt * 8 + 2 * c;
            Dt[r0 * DP + n0]           = acc[mt][nt][0];
            Dt[r0 * DP + n0 + 1]       = acc[mt][nt][1];
            Dt[(r0 + 8) * DP + n0]     = acc[mt][nt][2];
            Dt[(r0 + 8) * DP + n0 + 1] = acc[mt][nt][3];
        }
    }
    __syncthreads();
    for (int idx = tid; idx < O * 128; idx += 256) {
        int o = idx >> 7, tl = idx & 127;
        int t = t0 + tl;
        if (t < Tconv) {
            float v = Dt[tl * DP + o] + bias_sh[o];
            if (RELU) v = fmaxf(v, 0.f);
            size_t oi = ((size_t)b * O + o) * Tconv + t;
            if (OUT_PACKED) ((u32*)yv)[oi] = split1(v);
            else            ((float*)yv)[oi] = v;
        }
    }
}

// ---------------------------------------------------------------------------
// Masked adaptive-max over valid frames + 3-layer MLP head
// ---------------------------------------------------------------------------
__global__ void head_kernel(const float* __restrict__ y7,       // [64][128][14]
                            const int* __restrict__ len_mask,
                            const float* __restrict__ lw1, const float* __restrict__ lb1,
                            const float* __restrict__ lw2, const float* __restrict__ lb2,
                            const float* __restrict__ lw3, const float* __restrict__ lb3,
                            float* __restrict__ out) {
    __shared__ float v[128], h1[128], h2[64];
    const int b = blockIdx.x;
    const int tid = threadIdx.x;

    int L = len_mask[b];
    L = (L - 10) / 2 + 1;
    L = (L - 5) / 2 + 1;
    L = (L - 5) / 2 + 1;
    L = (L - 5) / 2 + 1;
    L >>= 1;
    L = (L - 5) / 2 + 1;
    L >>= 1;
    L = (L - 5) / 2 + 1;
    L = (L - 3) / 2 + 1;
    if (L > 14) L = 14;
    if (L < 1)  L = 1;

    const float* row = y7 + ((size_t)b * 128 + tid) * 14;
    float m = -3.4e38f;
    for (int t = 0; t < L; t++) m = fmaxf(m, row[t]);
    v[tid] = m;
    __syncthreads();

    float s = lb1[tid];
#pragma unroll 8
    for (int i = 0; i < 128; i++) s += lw1[tid * 128 + i] * v[i];
    h1[tid] = fmaxf(s, 0.f);
    __syncthreads();

    if (tid < 64) {
        float s2 = lb2[tid];
#pragma unroll 8
        for (int i = 0; i < 128; i++) s2 += lw2[tid * 128 + i] * h1[i];
        h2[tid] = fmaxf(s2, 0.f);
    }
    __syncthreads();

    if (tid < 5) {
        float s3 = lb3[tid];
#pragma unroll 8
        for (int i = 0; i < 64; i++) s3 += lw3[tid * 64 + i] * h2[i];
        out[b * 5 + tid] = s3;
    }
}

// ---------------------------------------------------------------------------
// Launch
// ---------------------------------------------------------------------------
extern "C" void kernel_launch(void* const* d_in, const int* in_sizes, int n_in,
                              void* d_out, int out_size) {
    const float* x    = (const float*)d_in[0];
    const int*   lenm = (const int*)d_in[1];
    const float* w1 = (const float*)d_in[2];  const float* b1 = (const float*)d_in[3];
    const float* w2 = (const float*)d_in[4];  const float* b2 = (const float*)d_in[5];
    const float* w3 = (const float*)d_in[6];  const float* b3 = (const float*)d_in[7];
    const float* w4 = (const float*)d_in[8];  const float* b4 = (const float*)d_in[9];
    const float* w5 = (const float*)d_in[10]; const float* b5 = (const float*)d_in[11];
    const float* w6 = (const float*)d_in[12]; const float* b6 = (const float*)d_in[13];
    const float* w7 = (const float*)d_in[14]; const float* b7 = (const float*)d_in[15];
    const float* lw1 = (const float*)d_in[16]; const float* lb1 = (const float*)d_in[17];
    const float* lw2 = (const float*)d_in[18]; const float* lb2 = (const float*)d_in[19];
    const float* lw3 = (const float*)d_in[20]; const float* lb3 = (const float*)d_in[21];

    u32* base = nullptr;
    cudaGetSymbolAddress((void**)&base, g_scratch);
    u16* wsp = nullptr;
    cudaGetSymbolAddress((void**)&wsp, g_wsplit);

    u32* B1 = base + OFF_B1;
    u32* B2 = base + OFF_B2;
    u32* B3 = base + OFF_B3;
    u32* B4 = base + OFF_B4;
    u32* B5 = base + OFF_B5;
    u32* B6 = base + OFF_B6;
    float* B7 = (float*)(base + OFF_B7);

    // kernels:                I   O    K  RELU  IN  OUTPK
    auto m1 = conv_hmma_kernel<40, 96, 10, true,  0, true>;
    auto m2 = conv_hmma_kernel<96, 96,  5, true,  1, true>;   // conv2, conv3
    auto m4 = conv_hmma_kernel<96, 96,  5, false, 1, true>;   // conv4
    auto m5 = conv_hmma_kernel<96, 96,  5, false, 2, true>;   // conv5 (pool in)
    auto m6 = conv_hmma_kernel<96, 96,  5, true,  2, true>;   // conv6 (pool in)
    auto m7 = conv_hmma_kernel<96, 128, 3, true,  1, false>;  // conv7 -> fp32

    const int SM1 = cx_smem(40, 10, 96);
    const int SM2 = cx_smem(96, 5, 96);
    const int SM7 = cx_smem(96, 3, 128);
    cudaFuncSetAttribute(m1, cudaFuncAttributeMaxDynamicSharedMemorySize, SM1);
    cudaFuncSetAttribute(m2, cudaFuncAttributeMaxDynamicSharedMemorySize, SM2);
    cudaFuncSetAttribute(m4, cudaFuncAttributeMaxDynamicSharedMemorySize, SM2);
    cudaFuncSetAttribute(m5, cudaFuncAttributeMaxDynamicSharedMemorySize, SM2);
    cudaFuncSetAttribute(m6, cudaFuncAttributeMaxDynamicSharedMemorySize, SM2);
    cudaFuncSetAttribute(m7, cudaFuncAttributeMaxDynamicSharedMemorySize, SM7);

    // 0: weight pre-split (all 7 conv weights, chunked layout)
    presplit_w_kernel<<<(329728 + 255) / 256, 256>>>(w1, w2, w3, w4, w5, w6, w7);

    // 1-7: HMMA convs, M tile = 128
    m1<<<dim3(32, 64), 256, SM1>>>(x,  wsp + W1H, wsp + W1L, b1, B1, 8192, 8192, 4092);
    m2<<<dim3(16, 64), 256, SM2>>>(B1, wsp + W2H, wsp + W2L, b2, B2, 4092, 4092, 2044);
    m2<<<dim3(8, 64),  256, SM2>>>(B2, wsp + W3H, wsp + W3L, b3, B3, 2044, 2044, 1020);
    m4<<<dim3(4, 64),  256, SM2>>>(B3, wsp + W4H, wsp + W4L, b4, B4, 1020, 1020, 508);
    m5<<<dim3(1, 64),  256, SM2>>>(B4, wsp + W5H, wsp + W5L, b5, B5, 254, 508, 125);
    m6<<<dim3(1, 64),  256, SM2>>>(B5, wsp + W6H, wsp + W6L, b6, B6, 62, 125, 29);
    m7<<<dim3(1, 64),  256, SM7>>>(B6, wsp + W7H, wsp + W7L, b7, B7, 29, 29, 14);

    // 8: masked max + MLP head
    head_kernel<<<64, 128>>>(B7, lenm, lw1, lb1, lw2, lb2, lw3, lb3,
                             (float*)d_out);
}

// round 16
// speedup vs baseline: 1.3011x; 1.3011x over previous
#include <cuda_runtime.h>
#include <cuda_bf16.h>
#include <cstdint>
#include <cstddef>

typedef unsigned long long u64;
typedef unsigned int u32;
typedef unsigned short u16;

// ---------------------------------------------------------------------------
// Scratch buffers (device globals; no allocations anywhere).
// B1..B6 hold packed bf16(hi,lo) u32 per element; B7 holds fp32.
// ---------------------------------------------------------------------------
static constexpr size_t S_B1 = 64ull * 96 * 4092;
static constexpr size_t S_B2 = 64ull * 96 * 2044;
static constexpr size_t S_B3 = 64ull * 96 * 1020;
static constexpr size_t S_B4 = 64ull * 96 * 508;
static constexpr size_t S_B5 = 64ull * 96 * 125;
static constexpr size_t S_B6 = 64ull * 96 * 29;
static constexpr size_t S_B7 = 64ull * 128 * 14;

static constexpr size_t OFF_B1 = 0;
static constexpr size_t OFF_B2 = OFF_B1 + S_B1;
static constexpr size_t OFF_B3 = OFF_B2 + S_B2;
static constexpr size_t OFF_B4 = OFF_B3 + S_B3;
static constexpr size_t OFF_B5 = OFF_B4 + S_B4;
static constexpr size_t OFF_B6 = OFF_B5 + S_B5;
static constexpr size_t OFF_B7 = OFF_B6 + S_B6;
static constexpr size_t SCRATCH_TOTAL = OFF_B7 + S_B7;

__device__ u32 g_scratch[SCRATCH_TOTAL];

// pre-split weights (bf16 hi/lo, chunk-padded [NCH][O][64], straight ik cols)
static constexpr int W1H = 0,      W1L = 43008;    // O=96  NCH=7
static constexpr int W2H = 86016,  W2L = 135168;   // O=96  NCH=8
static constexpr int W3H = 184320, W3L = 233472;
static constexpr int W4H = 282624, W4L = 331776;
static constexpr int W5H = 380928, W5L = 430080;
static constexpr int W6H = 479232, W6L = 528384;
static constexpr int W7H = 577536, W7L = 618496;   // O=128 NCH=5
__device__ __align__(256) u16 g_wsplit[659456];

// ---------------------------------------------------------------------------
// PTX helpers (baseline ISA only — compiles at compute_103)
// ---------------------------------------------------------------------------
__device__ __forceinline__ void ldsm_x4(u32* r, u32 addr) {
    asm volatile("ldmatrix.sync.aligned.m8n8.x4.shared.b16 {%0,%1,%2,%3}, [%4];"
                 : "=r"(r[0]), "=r"(r[1]), "=r"(r[2]), "=r"(r[3]) : "r"(addr));
}
__device__ __forceinline__ void ldsm_x2(u32* r, u32 addr) {
    asm volatile("ldmatrix.sync.aligned.m8n8.x2.shared.b16 {%0,%1}, [%2];"
                 : "=r"(r[0]), "=r"(r[1]) : "r"(addr));
}
__device__ __forceinline__ void mma_bf16(float* d, const u32* a, const u32* b) {
    asm volatile(
        "mma.sync.aligned.m16n8k16.row.col.f32.bf16.bf16.f32 "
        "{%0,%1,%2,%3}, {%4,%5,%6,%7}, {%8,%9}, {%0,%1,%2,%3};"
        : "+f"(d[0]), "+f"(d[1]), "+f"(d[2]), "+f"(d[3])
        : "r"(a[0]), "r"(a[1]), "r"(a[2]), "r"(a[3]), "r"(b[0]), "r"(b[1]));
}
#define CP_ASYNC16(dst, src) \
    asm volatile("cp.async.cg.shared.global [%0], [%1], 16;" \
                 :: "r"((u32)(dst)), "l"(src) : "memory")
#define CP_ASYNC_COMMIT() asm volatile("cp.async.commit_group;" ::: "memory")
#define CP_ASYNC_WAIT0()  asm volatile("cp.async.wait_group 0;" ::: "memory")
#define STS128(addr, a, b, c, d) \
    asm volatile("st.shared.v4.b32 [%0], {%1, %2, %3, %4};" \
                 :: "r"((u32)(addr)), "r"(a), "r"(b), "r"(c), "r"(d) : "memory")

__device__ __forceinline__ u32 smem_u32(const void* p) {
    u32 a;
    asm("{ .reg .u64 t; cvta.to.shared.u64 t, %1; cvt.u32.u64 %0, t; }"
        : "=r"(a) : "l"(p));
    return a;
}

// fp32 -> packed (bf16 hi | bf16 lo << 16), value ~= hi + lo
__device__ __forceinline__ u32 split1(float v) {
    __nv_bfloat16 h = __float2bfloat16_rn(v);
    __nv_bfloat16 l = __float2bfloat16_rn(v - __bfloat162float(h));
    return (u32)__bfloat16_as_ushort(h) | ((u32)__bfloat16_as_ushort(l) << 16);
}
__device__ __forceinline__ float unsplit1(u32 p) {
    return __bfloat162float(__ushort_as_bfloat16((u16)(p & 0xFFFF))) +
           __bfloat162float(__ushort_as_bfloat16((u16)(p >> 16)));
}

// smem layout (bytes); M tile = 64, row pitch 144B
__host__ __device__ constexpr int hx_xp(int K) { return (128 + K + 3) & ~3; }
__host__ __device__ constexpr int hx_ahi(int I, int K) {
    return (512 + I * hx_xp(K) * 4 + 15) & ~15;
}
__host__ __device__ constexpr int hx_smem(int I, int K, int O) {
    int total = hx_ahi(I, K) + 2 * 64 * 144 + 2 * O * 144;
    int dmin = 512 + 64 * (O + 1) * 4;
    return total > dmin ? total : dmin;
}

// ---------------------------------------------------------------------------
// Weight pre-split: w[O][IK] f32 -> [NCH][O][64] bf16 hi/lo (zero-padded)
// ---------------------------------------------------------------------------
__global__ void presplit_w_kernel(
    const float* __restrict__ w1, const float* __restrict__ w2,
    const float* __restrict__ w3, const float* __restrict__ w4,
    const float* __restrict__ w5, const float* __restrict__ w6,
    const float* __restrict__ w7) {
    int n = blockIdx.x * blockDim.x + threadIdx.x;
    const float* w; int IK, O; u16 *hi, *lo; int idx;
    if      (n < 43008)  { w = w1; IK = 400; O = 96;  hi = g_wsplit + W1H; lo = g_wsplit + W1L; idx = n; }
    else if (n < 92160)  { w = w2; IK = 480; O = 96;  hi = g_wsplit + W2H; lo = g_wsplit + W2L; idx = n - 43008; }
    else if (n < 141312) { w = w3; IK = 480; O = 96;  hi = g_wsplit + W3H; lo = g_wsplit + W3L; idx = n - 92160; }
    else if (n < 190464) { w = w4; IK = 480; O = 96;  hi = g_wsplit + W4H; lo = g_wsplit + W4L; idx = n - 141312; }
    else if (n < 239616) { w = w5; IK = 480; O = 96;  hi = g_wsplit + W5H; lo = g_wsplit + W5L; idx = n - 190464; }
    else if (n < 288768) { w = w6; IK = 480; O = 96;  hi = g_wsplit + W6H; lo = g_wsplit + W6L; idx = n - 239616; }
    else if (n < 329728) { w = w7; IK = 288; O = 128; hi = g_wsplit + W7H; lo = g_wsplit + W7L; idx = n - 288768; }
    else return;
    int c  = idx & 63;
    int o  = (idx >> 6) % O;
    int ch = idx / (64 * O);
    int cg = ch * 64 + c;
    float v = (cg < IK) ? w[o * IK + cg] : 0.f;
    u32 p = split1(v);
    hi[idx] = (u16)(p & 0xFFFF);
    lo[idx] = (u16)(p >> 16);
}

// ---------------------------------------------------------------------------
// Implicit-GEMM conv via HMMA, bf16 split, 3 passes. M tile = 64.
// 8 warps = 2 m-warps (m32) x 4 n-warps (n = O/4): B smem re-read x2 (was x4),
// the crossbar-dominant term. Chunk loop, staging, grids identical to the
// proven 653.8us kernel. 2 CTAs/SM.
// IN_MODE: 0 = fp32 input, 1 = packed u32 input, 2 = packed + avgpool2 + relu
// ---------------------------------------------------------------------------
template <int I, int O, int K, bool RELU, int IN_MODE, bool OUT_PACKED>
__global__ __launch_bounds__(256, 2)
void conv_hmma_kernel(const void* __restrict__ xv,
                      const u16* __restrict__ whi, const u16* __restrict__ wlo,
                      const float* __restrict__ bias, void* __restrict__ yv,
                      int Tin, int TinRaw, int Tconv) {
    constexpr int IK = I * K;
    constexpr int NCH = (IK + 63) / 64;
    constexpr int USPAN = 128 + K;
    constexpr int XP = hx_xp(K);
    constexpr int A_HI = hx_ahi(I, K);
    constexpr int A_LO = A_HI + 64 * 144;
    constexpr int B_HI = A_LO + 64 * 144;
    constexpr int B_LO = B_HI + O * 144;
    constexpr int NPW = O / 4;           // n cols per n-warp (24 or 32)
    constexpr int NTILE = NPW / 8;       // n8 tiles per warp (3 or 4)
    constexpr int DP = O + 1;            // epilogue smem pitch
    static_assert(IK % 8 == 0, "IK mult of 8");

    extern __shared__ char smem[];
    const u32 sm = smem_u32(smem);
    float* bias_sh = reinterpret_cast<float*>(smem);
    u32*   xsp     = reinterpret_cast<u32*>(smem + 512);

    const int b    = blockIdx.y;
    const int t0   = blockIdx.x * 64;
    const int tid  = threadIdx.x;
    const int wid  = tid >> 5;
    const int lane = tid & 31;
    const int mw   = wid & 1;                // 2 m-warps (m32 each)
    const int nw   = wid >> 1;               // 4 n-warps (NPW cols each)

    if (tid < O) bias_sh[tid] = bias[tid];

    // stage input slice once as packed (hi,lo) u32s
    for (int n = tid; n < I * USPAN; n += 256) {
        int i = n / USPAN;
        int u = n - i * USPAN;
        int tg = 2 * t0 + u;
        u32 pv = 0;
        if (tg < Tin) {
            if (IN_MODE == 0) {
                const float* xf = (const float*)xv;
                pv = split1(xf[((size_t)b * I + i) * Tin + tg]);
            } else if (IN_MODE == 1) {
                const u32* xu = (const u32*)xv;
                pv = xu[((size_t)b * I + i) * Tin + tg];
            } else {
                const u32* xu = (const u32*)xv;
                const u32* row = xu + ((size_t)b * I + i) * TinRaw + 2 * tg;
                float f = 0.5f * (unsplit1(row[0]) + unsplit1(row[1]));
                pv = split1(fmaxf(f, 0.f));
            }
        }
        xsp[i * XP + u] = pv;
    }

    // ldsm lane offsets
    const u32 a_loff = (u32)((32 * mw + (lane & 7) + ((lane >> 3) & 1) * 8) * 144
                             + (lane >> 4) * 16);
    const u32 b4_loff = (u32)((nw * NPW + ((lane >> 4) << 3) + (lane & 7)) * 144
                              + ((lane >> 3) & 1) * 16);
    const int bl = lane & 15;
    const u32 b2_loff = (u32)((nw * NPW + (NTILE - 1) * 8 + (bl & 7)) * 144
                              + (bl >> 3) * 16);

    float acc[2][NTILE][4];
#pragma unroll
    for (int mt = 0; mt < 2; mt++)
#pragma unroll
        for (int nt = 0; nt < NTILE; nt++)
#pragma unroll
            for (int q = 0; q < 4; q++) acc[mt][nt][q] = 0.f;

    __syncthreads();   // xsp ready

    for (int ch = 0; ch < NCH; ch++) {
        if (ch) __syncthreads();   // previous compute finished

        // B: cp.async from pre-split gmem (O rows x 128B, hi + lo)
        {
            const u16* srcH = whi + (size_t)ch * O * 64;
            const u16* srcL = wlo + (size_t)ch * O * 64;
            for (int s = tid; s < O * 8; s += 256) {
                int o = s >> 3, seg = s & 7;
                CP_ASYNC16(sm + B_HI + o * 144 + seg * 16, srcH + o * 64 + seg * 8);
                CP_ASYNC16(sm + B_LO + o * 144 + seg * 16, srcL + o * 64 + seg * 8);
            }
            CP_ASYNC_COMMIT();
        }

        // A: im2col gather from xsp (packed), PRMT split into hi/lo tiles
        for (int unit = tid; unit < 512; unit += 256) {
            int t = unit >> 3, g = unit & 7;
            int cg0 = ch * 64 + g * 8;
            u32 ph[4], pl[4];
            if (cg0 < IK) {
                u32 s[8];
#pragma unroll
                for (int e = 0; e < 8; e++) {
                    int cg = cg0 + e;
                    int i = cg / K;
                    int k = cg - i * K;
                    s[e] = xsp[i * XP + 2 * t + k];
                }
#pragma unroll
                for (int e2 = 0; e2 < 4; e2++) {
                    ph[e2] = __byte_perm(s[2 * e2], s[2 * e2 + 1], 0x5410);
                    pl[e2] = __byte_perm(s[2 * e2], s[2 * e2 + 1], 0x7632);
                }
            } else {
#pragma unroll
                for (int e2 = 0; e2 < 4; e2++) { ph[e2] = 0; pl[e2] = 0; }
            }
            u32 off = (u32)(t * 144 + g * 16);
            STS128(sm + A_HI + off, ph[0], ph[1], ph[2], ph[3]);
            STS128(sm + A_LO + off, pl[0], pl[1], pl[2], pl[3]);
        }

        CP_ASYNC_WAIT0();
        __syncthreads();

        // compute: 4 k-steps; pass-major (acc reuse distance = 2*NTILE)
        const u32 ah_b = sm + A_HI + a_loff;
        const u32 al_b = sm + A_LO + a_loff;
#pragma unroll
        for (int ks = 0; ks < 4; ks++) {
            u32 ahi[2][4], alo[2][4];
#pragma unroll
            for (int mt = 0; mt < 2; mt++) {
                ldsm_x4(ahi[mt], ah_b + (u32)(mt * 16 * 144) + ks * 32);
                ldsm_x4(alo[mt], al_b + (u32)(mt * 16 * 144) + ks * 32);
            }
            u32 bh[2 * NTILE], blr[2 * NTILE];
#pragma unroll
            for (int p = 0; p < NTILE / 2; p++) {
                ldsm_x4(bh + 4 * p, sm + B_HI + b4_loff + (u32)(p * 16 * 144) + ks * 32);
                ldsm_x4(blr + 4 * p, sm + B_LO + b4_loff + (u32)(p * 16 * 144) + ks * 32);
            }
            if (NTILE & 1) {
                ldsm_x2(bh + 2 * (NTILE - 1), sm + B_HI + b2_loff + ks * 32);
                ldsm_x2(blr + 2 * (NTILE - 1), sm + B_LO + b2_loff + ks * 32);
            }
#pragma unroll
            for (int nt = 0; nt < NTILE; nt++)
#pragma unroll
                for (int mt = 0; mt < 2; mt++)
                    mma_bf16(acc[mt][nt], ahi[mt], bh + 2 * nt);
#pragma unroll
            for (int nt = 0; nt < NTILE; nt++)
#pragma unroll
                for (int mt = 0; mt < 2; mt++)
                    mma_bf16(acc[mt][nt], ahi[mt], blr + 2 * nt);
#pragma unroll
            for (int nt = 0; nt < NTILE; nt++)
#pragma unroll
                for (int mt = 0; mt < 2; mt++)
                    mma_bf16(acc[mt][nt], alo[mt], bh + 2 * nt);
        }
    }

    // epilogue: frags -> smem (pitch DP) -> coalesced gmem
    __syncthreads();
    float* Dt = reinterpret_cast<float*>(smem + 512);
    const int g = lane >> 2, c = lane & 3;
#pragma unroll
    for (int mt = 0; mt < 2; mt++) {
        const int r0 = 32 * mw + 16 * mt + g;
#pragma unroll
        for (int nt = 0; nt < NTILE; nt++) {
            int n0 = nw * NPW + nt * 8 + 2 * c;
            Dt[r0 * DP + n0]           = acc[mt][nt][0];
            Dt[r0 * DP + n0 + 1]       = acc[mt][nt][1];
            Dt[(r0 + 8) * DP + n0]     = acc[mt][nt][2];
            Dt[(r0 + 8) * DP + n0 + 1] = acc[mt][nt][3];
        }
    }
    __syncthreads();
    for (int idx = tid; idx < O * 64; idx += 256) {
        int o = idx >> 6, tl = idx & 63;
        int t = t0 + tl;
        if (t < Tconv) {
            float v = Dt[tl * DP + o] + bias_sh[o];
            if (RELU) v = fmaxf(v, 0.f);
            size_t oi = ((size_t)b * O + o) * Tconv + t;
            if (OUT_PACKED) ((u32*)yv)[oi] = split1(v);
            else            ((float*)yv)[oi] = v;
        }
    }
}

// ---------------------------------------------------------------------------
// Masked adaptive-max over valid frames + 3-layer MLP head
// ---------------------------------------------------------------------------
__global__ void head_kernel(const float* __restrict__ y7,       // [64][128][14]
                            const int* __restrict__ len_mask,
                            const float* __restrict__ lw1, const float* __restrict__ lb1,
                            const float* __restrict__ lw2, const float* __restrict__ lb2,
                            const float* __restrict__ lw3, const float* __restrict__ lb3,
                            float* __restrict__ out) {
    __shared__ float v[128], h1[128], h2[64];
    const int b = blockIdx.x;
    const int tid = threadIdx.x;

    int L = len_mask[b];
    L = (L - 10) / 2 + 1;
    L = (L - 5) / 2 + 1;
    L = (L - 5) / 2 + 1;
    L = (L - 5) / 2 + 1;
    L >>= 1;
    L = (L - 5) / 2 + 1;
    L >>= 1;
    L = (L - 5) / 2 + 1;
    L = (L - 3) / 2 + 1;
    if (L > 14) L = 14;
    if (L < 1)  L = 1;

    const float* row = y7 + ((size_t)b * 128 + tid) * 14;
    float m = -3.4e38f;
    for (int t = 0; t < L; t++) m = fmaxf(m, row[t]);
    v[tid] = m;
    __syncthreads();

    float s = lb1[tid];
#pragma unroll 8
    for (int i = 0; i < 128; i++) s += lw1[tid * 128 + i] * v[i];
    h1[tid] = fmaxf(s, 0.f);
    __syncthreads();

    if (tid < 64) {
        float s2 = lb2[tid];
#pragma unroll 8
        for (int i = 0; i < 128; i++) s2 += lw2[tid * 128 + i] * h1[i];
        h2[tid] = fmaxf(s2, 0.f);
    }
    __syncthreads();

    if (tid < 5) {
        float s3 = lb3[tid];
#pragma unroll 8
        for (int i = 0; i < 64; i++) s3 += lw3[tid * 64 + i] * h2[i];
        out[b * 5 + tid] = s3;
    }
}

// ---------------------------------------------------------------------------
// Launch
// ---------------------------------------------------------------------------
extern "C" void kernel_launch(void* const* d_in, const int* in_sizes, int n_in,
                              void* d_out, int out_size) {
    const float* x    = (const float*)d_in[0];
    const int*   lenm = (const int*)d_in[1];
    const float* w1 = (const float*)d_in[2];  const float* b1 = (const float*)d_in[3];
    const float* w2 = (const float*)d_in[4];  const float* b2 = (const float*)d_in[5];
    const float* w3 = (const float*)d_in[6];  const float* b3 = (const float*)d_in[7];
    const float* w4 = (const float*)d_in[8];  const float* b4 = (const float*)d_in[9];
    const float* w5 = (const float*)d_in[10]; const float* b5 = (const float*)d_in[11];
    const float* w6 = (const float*)d_in[12]; const float* b6 = (const float*)d_in[13];
    const float* w7 = (const float*)d_in[14]; const float* b7 = (const float*)d_in[15];
    const float* lw1 = (const float*)d_in[16]; const float* lb1 = (const float*)d_in[17];
    const float* lw2 = (const float*)d_in[18]; const float* lb2 = (const float*)d_in[19];
    const float* lw3 = (const float*)d_in[20]; const float* lb3 = (const float*)d_in[21];

    u32* base = nullptr;
    cudaGetSymbolAddress((void**)&base, g_scratch);
    u16* wsp = nullptr;
    cudaGetSymbolAddress((void**)&wsp, g_wsplit);

    u32* B1 = base + OFF_B1;
    u32* B2 = base + OFF_B2;
    u32* B3 = base + OFF_B3;
    u32* B4 = base + OFF_B4;
    u32* B5 = base + OFF_B5;
    u32* B6 = base + OFF_B6;
    float* B7 = (float*)(base + OFF_B7);

    // kernels:                I   O    K  RELU  IN  OUTPK
    auto m1 = conv_hmma_kernel<40, 96, 10, true,  0, true>;
    auto m2 = conv_hmma_kernel<96, 96,  5, true,  1, true>;   // conv2, conv3
    auto m4 = conv_hmma_kernel<96, 96,  5, false, 1, true>;   // conv4
    auto m5 = conv_hmma_kernel<96, 96,  5, false, 2, true>;   // conv5 (pool in)
    auto m6 = conv_hmma_kernel<96, 96,  5, true,  2, true>;   // conv6 (pool in)
    auto m7 = conv_hmma_kernel<96, 128, 3, true,  1, false>;  // conv7 -> fp32

    const int SM1 = hx_smem(40, 10, 96);
    const int SM2 = hx_smem(96, 5, 96);
    const int SM7 = hx_smem(96, 3, 128);
    cudaFuncSetAttribute(m1, cudaFuncAttributeMaxDynamicSharedMemorySize, SM1);
    cudaFuncSetAttribute(m2, cudaFuncAttributeMaxDynamicSharedMemorySize, SM2);
    cudaFuncSetAttribute(m4, cudaFuncAttributeMaxDynamicSharedMemorySize, SM2);
    cudaFuncSetAttribute(m5, cudaFuncAttributeMaxDynamicSharedMemorySize, SM2);
    cudaFuncSetAttribute(m6, cudaFuncAttributeMaxDynamicSharedMemorySize, SM2);
    cudaFuncSetAttribute(m7, cudaFuncAttributeMaxDynamicSharedMemorySize, SM7);

    // 0: weight pre-split (all 7 conv weights)
    presplit_w_kernel<<<(329728 + 255) / 256, 256>>>(w1, w2, w3, w4, w5, w6, w7);

    // 1-7: HMMA convs (M tile 64, grids as in the 653.8us kernel)
    m1<<<dim3(64, 64), 256, SM1>>>(x,  wsp + W1H, wsp + W1L, b1, B1, 8192, 8192, 4092);
    m2<<<dim3(32, 64), 256, SM2>>>(B1, wsp + W2H, wsp + W2L, b2, B2, 4092, 4092, 2044);
    m2<<<dim3(16, 64), 256, SM2>>>(B2, wsp + W3H, wsp + W3L, b3, B3, 2044, 2044, 1020);
    m4<<<dim3(8, 64),  256, SM2>>>(B3, wsp + W4H, wsp + W4L, b4, B4, 1020, 1020, 508);
    m5<<<dim3(2, 64),  256, SM2>>>(B4, wsp + W5H, wsp + W5L, b5, B5, 254, 508, 125);
    m6<<<dim3(1, 64),  256, SM2>>>(B5, wsp + W6H, wsp + W6L, b6, B6, 62, 125, 29);
    m7<<<dim3(1, 64),  256, SM7>>>(B6, wsp + W7H, wsp + W7L, b7, B7, 29, 29, 14);

    // 8: masked max + MLP head
    head_kernel<<<64, 128>>>(B7, lenm, lw1, lb1, lw2, lb2, lw3, lb3,
                             (float*)d_out);
}

// round 17
// speedup vs baseline: 1.3734x; 1.0556x over previous
#include <cuda_runtime.h>
#include <cuda_bf16.h>
#include <cstdint>
#include <cstddef>

typedef unsigned long long u64;
typedef unsigned int u32;
typedef unsigned short u16;

// ---------------------------------------------------------------------------
// Scratch buffers (device globals; no allocations anywhere).
// B1..B6 hold packed bf16(hi,lo) u32 per element; B7 holds fp32.
// ---------------------------------------------------------------------------
static constexpr size_t S_B1 = 64ull * 96 * 4092;
static constexpr size_t S_B2 = 64ull * 96 * 2044;
static constexpr size_t S_B3 = 64ull * 96 * 1020;
static constexpr size_t S_B4 = 64ull * 96 * 508;
static constexpr size_t S_B5 = 64ull * 96 * 125;
static constexpr size_t S_B6 = 64ull * 96 * 29;
static constexpr size_t S_B7 = 64ull * 128 * 14;

static constexpr size_t OFF_B1 = 0;
static constexpr size_t OFF_B2 = OFF_B1 + S_B1;
static constexpr size_t OFF_B3 = OFF_B2 + S_B2;
static constexpr size_t OFF_B4 = OFF_B3 + S_B3;
static constexpr size_t OFF_B5 = OFF_B4 + S_B4;
static constexpr size_t OFF_B6 = OFF_B5 + S_B5;
static constexpr size_t OFF_B7 = OFF_B6 + S_B6;
static constexpr size_t SCRATCH_TOTAL = OFF_B7 + S_B7;

__device__ u32 g_scratch[SCRATCH_TOTAL];

// pre-split weights (bf16 hi/lo, chunk-padded [NCH][O][64], straight ik cols)
static constexpr int W1H = 0,      W1L = 43008;    // O=96  NCH=7
static constexpr int W2H = 86016,  W2L = 135168;   // O=96  NCH=8
static constexpr int W3H = 184320, W3L = 233472;
static constexpr int W4H = 282624, W4L = 331776;
static constexpr int W5H = 380928, W5L = 430080;
static constexpr int W6H = 479232, W6L = 528384;
static constexpr int W7H = 577536, W7L = 618496;   // O=128 NCH=5
__device__ __align__(256) u16 g_wsplit[659456];

// ---------------------------------------------------------------------------
// PTX helpers (baseline ISA only — compiles at compute_103)
// ---------------------------------------------------------------------------
__device__ __forceinline__ void ldsm_x4(u32* r, u32 addr) {
    asm volatile("ldmatrix.sync.aligned.m8n8.x4.shared.b16 {%0,%1,%2,%3}, [%4];"
                 : "=r"(r[0]), "=r"(r[1]), "=r"(r[2]), "=r"(r[3]) : "r"(addr));
}
__device__ __forceinline__ void ldsm_x2(u32* r, u32 addr) {
    asm volatile("ldmatrix.sync.aligned.m8n8.x2.shared.b16 {%0,%1}, [%2];"
                 : "=r"(r[0]), "=r"(r[1]) : "r"(addr));
}
__device__ __forceinline__ void mma_bf16(float* d, const u32* a, const u32* b) {
    asm volatile(
        "mma.sync.aligned.m16n8k16.row.col.f32.bf16.bf16.f32 "
        "{%0,%1,%2,%3}, {%4,%5,%6,%7}, {%8,%9}, {%0,%1,%2,%3};"
        : "+f"(d[0]), "+f"(d[1]), "+f"(d[2]), "+f"(d[3])
        : "r"(a[0]), "r"(a[1]), "r"(a[2]), "r"(a[3]), "r"(b[0]), "r"(b[1]));
}
#define CP_ASYNC16(dst, src) \
    asm volatile("cp.async.cg.shared.global [%0], [%1], 16;" \
                 :: "r"((u32)(dst)), "l"(src) : "memory")
#define CP_ASYNC_COMMIT() asm volatile("cp.async.commit_group;" ::: "memory")
#define CP_ASYNC_WAIT0()  asm volatile("cp.async.wait_group 0;" ::: "memory")
#define STS128(addr, a, b, c, d) \
    asm volatile("st.shared.v4.b32 [%0], {%1, %2, %3, %4};" \
                 :: "r"((u32)(addr)), "r"(a), "r"(b), "r"(c), "r"(d) : "memory")

__device__ __forceinline__ u32 smem_u32(const void* p) {
    u32 a;
    asm("{ .reg .u64 t; cvta.to.shared.u64 t, %1; cvt.u32.u64 %0, t; }"
        : "=r"(a) : "l"(p));
    return a;
}

// fp32 -> packed (bf16 hi | bf16 lo << 16), value ~= hi + lo
__device__ __forceinline__ u32 split1(float v) {
    __nv_bfloat16 h = __float2bfloat16_rn(v);
    __nv_bfloat16 l = __float2bfloat16_rn(v - __bfloat162float(h));
    return (u32)__bfloat16_as_ushort(h) | ((u32)__bfloat16_as_ushort(l) << 16);
}
__device__ __forceinline__ float unsplit1(u32 p) {
    return __bfloat162float(__ushort_as_bfloat16((u16)(p & 0xFFFF))) +
           __bfloat162float(__ushort_as_bfloat16((u16)(p >> 16)));
}

// smem layout (bytes); M tile = 64, row pitch 144B
__host__ __device__ constexpr int hx_xp(int K) { return (128 + K + 3) & ~3; }
__host__ __device__ constexpr int hx_ahi(int I, int K) {
    return (512 + I * hx_xp(K) * 4 + 15) & ~15;
}
__host__ __device__ constexpr int hx_smem(int I, int K, int O) {
    int total = hx_ahi(I, K) + 2 * 64 * 144 + 2 * O * 144;
    int dmin = 512 + 64 * (O + 1) * 4;
    return total > dmin ? total : dmin;
}

// ---------------------------------------------------------------------------
// Weight pre-split: w[O][IK] f32 -> [NCH][O][64] bf16 hi/lo (zero-padded)
// ---------------------------------------------------------------------------
__global__ void presplit_w_kernel(
    const float* __restrict__ w1, const float* __restrict__ w2,
    const float* __restrict__ w3, const float* __restrict__ w4,
    const float* __restrict__ w5, const float* __restrict__ w6,
    const float* __restrict__ w7) {
    int n = blockIdx.x * blockDim.x + threadIdx.x;
    const float* w; int IK, O; u16 *hi, *lo; int idx;
    if      (n < 43008)  { w = w1; IK = 400; O = 96;  hi = g_wsplit + W1H; lo = g_wsplit + W1L; idx = n; }
    else if (n < 92160)  { w = w2; IK = 480; O = 96;  hi = g_wsplit + W2H; lo = g_wsplit + W2L; idx = n - 43008; }
    else if (n < 141312) { w = w3; IK = 480; O = 96;  hi = g_wsplit + W3H; lo = g_wsplit + W3L; idx = n - 92160; }
    else if (n < 190464) { w = w4; IK = 480; O = 96;  hi = g_wsplit + W4H; lo = g_wsplit + W4L; idx = n - 141312; }
    else if (n < 239616) { w = w5; IK = 480; O = 96;  hi = g_wsplit + W5H; lo = g_wsplit + W5L; idx = n - 190464; }
    else if (n < 288768) { w = w6; IK = 480; O = 96;  hi = g_wsplit + W6H; lo = g_wsplit + W6L; idx = n - 239616; }
    else if (n < 329728) { w = w7; IK = 288; O = 128; hi = g_wsplit + W7H; lo = g_wsplit + W7L; idx = n - 288768; }
    else return;
    int c  = idx & 63;
    int o  = (idx >> 6) % O;
    int ch = idx / (64 * O);
    int cg = ch * 64 + c;
    float v = (cg < IK) ? w[o * IK + cg] : 0.f;
    u32 p = split1(v);
    hi[idx] = (u16)(p & 0xFFFF);
    lo[idx] = (u16)(p >> 16);
}

// ---------------------------------------------------------------------------
// Implicit-GEMM conv via HMMA, bf16 split, 3 passes. M tile = 64.
// 8 warps = 2 m-warps (m32) x 4 n-warps (n = O/4). OCC = CTAs/SM target:
// conv1 (smem ~67KB) runs at 3 CTAs/SM for issue-slot coverage; others at 2.
// IN_MODE: 0 = fp32 input, 1 = packed u32 input, 2 = packed + avgpool2 + relu
// ---------------------------------------------------------------------------
template <int I, int O, int K, bool RELU, int IN_MODE, bool OUT_PACKED, int OCC>
__global__ __launch_bounds__(256, OCC)
void conv_hmma_kernel(const void* __restrict__ xv,
                      const u16* __restrict__ whi, const u16* __restrict__ wlo,
                      const float* __restrict__ bias, void* __restrict__ yv,
                      int Tin, int TinRaw, int Tconv) {
    constexpr int IK = I * K;
    constexpr int NCH = (IK + 63) / 64;
    constexpr int USPAN = 128 + K;
    constexpr int XP = hx_xp(K);
    constexpr int A_HI = hx_ahi(I, K);
    constexpr int A_LO = A_HI + 64 * 144;
    constexpr int B_HI = A_LO + 64 * 144;
    constexpr int B_LO = B_HI + O * 144;
    constexpr int NPW = O / 4;           // n cols per n-warp (24 or 32)
    constexpr int NTILE = NPW / 8;       // n8 tiles per warp (3 or 4)
    constexpr int DP = O + 1;            // epilogue smem pitch
    static_assert(IK % 8 == 0, "IK mult of 8");

    extern __shared__ char smem[];
    const u32 sm = smem_u32(smem);
    float* bias_sh = reinterpret_cast<float*>(smem);
    u32*   xsp     = reinterpret_cast<u32*>(smem + 512);

    const int b    = blockIdx.y;
    const int t0   = blockIdx.x * 64;
    const int tid  = threadIdx.x;
    const int wid  = tid >> 5;
    const int lane = tid & 31;
    const int mw   = wid & 1;                // 2 m-warps (m32 each)
    const int nw   = wid >> 1;               // 4 n-warps (NPW cols each)

    if (tid < O) bias_sh[tid] = bias[tid];

    // stage input slice once as packed (hi,lo) u32s
    for (int n = tid; n < I * USPAN; n += 256) {
        int i = n / USPAN;
        int u = n - i * USPAN;
        int tg = 2 * t0 + u;
        u32 pv = 0;
        if (tg < Tin) {
            if (IN_MODE == 0) {
                const float* xf = (const float*)xv;
                pv = split1(xf[((size_t)b * I + i) * Tin + tg]);
            } else if (IN_MODE == 1) {
                const u32* xu = (const u32*)xv;
                pv = xu[((size_t)b * I + i) * Tin + tg];
            } else {
                const u32* xu = (const u32*)xv;
                const u32* row = xu + ((size_t)b * I + i) * TinRaw + 2 * tg;
                float f = 0.5f * (unsplit1(row[0]) + unsplit1(row[1]));
                pv = split1(fmaxf(f, 0.f));
            }
        }
        xsp[i * XP + u] = pv;
    }

    // ldsm lane offsets
    const u32 a_loff = (u32)((32 * mw + (lane & 7) + ((lane >> 3) & 1) * 8) * 144
                             + (lane >> 4) * 16);
    const u32 b4_loff = (u32)((nw * NPW + ((lane >> 4) << 3) + (lane & 7)) * 144
                              + ((lane >> 3) & 1) * 16);
    const int bl = lane & 15;
    const u32 b2_loff = (u32)((nw * NPW + (NTILE - 1) * 8 + (bl & 7)) * 144
                              + (bl >> 3) * 16);

    float acc[2][NTILE][4];
#pragma unroll
    for (int mt = 0; mt < 2; mt++)
#pragma unroll
        for (int nt = 0; nt < NTILE; nt++)
#pragma unroll
            for (int q = 0; q < 4; q++) acc[mt][nt][q] = 0.f;

    __syncthreads();   // xsp ready

    for (int ch = 0; ch < NCH; ch++) {
        if (ch) __syncthreads();   // previous compute finished

        // B: cp.async from pre-split gmem (O rows x 128B, hi + lo)
        {
            const u16* srcH = whi + (size_t)ch * O * 64;
            const u16* srcL = wlo + (size_t)ch * O * 64;
            for (int s = tid; s < O * 8; s += 256) {
                int o = s >> 3, seg = s & 7;
                CP_ASYNC16(sm + B_HI + o * 144 + seg * 16, srcH + o * 64 + seg * 8);
                CP_ASYNC16(sm + B_LO + o * 144 + seg * 16, srcL + o * 64 + seg * 8);
            }
            CP_ASYNC_COMMIT();
        }

        // A: im2col gather from xsp (packed), PRMT split into hi/lo tiles
        for (int unit = tid; unit < 512; unit += 256) {
            int t = unit >> 3, g = unit & 7;
            int cg0 = ch * 64 + g * 8;
            u32 ph[4], pl[4];
            if (cg0 < IK) {
                u32 s[8];
#pragma unroll
                for (int e = 0; e < 8; e++) {
                    int cg = cg0 + e;
                    int i = cg / K;
                    int k = cg - i * K;
                    s[e] = xsp[i * XP + 2 * t + k];
                }
#pragma unroll
                for (int e2 = 0; e2 < 4; e2++) {
                    ph[e2] = __byte_perm(s[2 * e2], s[2 * e2 + 1], 0x5410);
                    pl[e2] = __byte_perm(s[2 * e2], s[2 * e2 + 1], 0x7632);
                }
            } else {
#pragma unroll
                for (int e2 = 0; e2 < 4; e2++) { ph[e2] = 0; pl[e2] = 0; }
            }
            u32 off = (u32)(t * 144 + g * 16);
            STS128(sm + A_HI + off, ph[0], ph[1], ph[2], ph[3]);
            STS128(sm + A_LO + off, pl[0], pl[1], pl[2], pl[3]);
        }

        CP_ASYNC_WAIT0();
        __syncthreads();

        // compute: 4 k-steps; pass-major (acc reuse distance = 2*NTILE)
        const u32 ah_b = sm + A_HI + a_loff;
        const u32 al_b = sm + A_LO + a_loff;
#pragma unroll
        for (int ks = 0; ks < 4; ks++) {
            u32 ahi[2][4], alo[2][4];
#pragma unroll
            for (int mt = 0; mt < 2; mt++) {
                ldsm_x4(ahi[mt], ah_b + (u32)(mt * 16 * 144) + ks * 32);
                ldsm_x4(alo[mt], al_b + (u32)(mt * 16 * 144) + ks * 32);
            }
            u32 bh[2 * NTILE], blr[2 * NTILE];
#pragma unroll
            for (int p = 0; p < NTILE / 2; p++) {
                ldsm_x4(bh + 4 * p, sm + B_HI + b4_loff + (u32)(p * 16 * 144) + ks * 32);
                ldsm_x4(blr + 4 * p, sm + B_LO + b4_loff + (u32)(p * 16 * 144) + ks * 32);
            }
            if (NTILE & 1) {
                ldsm_x2(bh + 2 * (NTILE - 1), sm + B_HI + b2_loff + ks * 32);
                ldsm_x2(blr + 2 * (NTILE - 1), sm + B_LO + b2_loff + ks * 32);
            }
#pragma unroll
            for (int nt = 0; nt < NTILE; nt++)
#pragma unroll
                for (int mt = 0; mt < 2; mt++)
                    mma_bf16(acc[mt][nt], ahi[mt], bh + 2 * nt);
#pragma unroll
            for (int nt = 0; nt < NTILE; nt++)
#pragma unroll
                for (int mt = 0; mt < 2; mt++)
                    mma_bf16(acc[mt][nt], ahi[mt], blr + 2 * nt);
#pragma unroll
            for (int nt = 0; nt < NTILE; nt++)
#pragma unroll
                for (int mt = 0; mt < 2; mt++)
                    mma_bf16(acc[mt][nt], alo[mt], bh + 2 * nt);
        }
    }

    // epilogue: frags -> smem (pitch DP) -> coalesced gmem
    __syncthreads();
    float* Dt = reinterpret_cast<float*>(smem + 512);
    const int g = lane >> 2, c = lane & 3;
#pragma unroll
    for (int mt = 0; mt < 2; mt++) {
        const int r0 = 32 * mw + 16 * mt + g;
#pragma unroll
        for (int nt = 0; nt < NTILE; nt++) {
            int n0 = nw * NPW + nt * 8 + 2 * c;
            Dt[r0 * DP + n0]           = acc[mt][nt][0];
            Dt[r0 * DP + n0 + 1]       = acc[mt][nt][1];
            Dt[(r0 + 8) * DP + n0]     = acc[mt][nt][2];
            Dt[(r0 + 8) * DP + n0 + 1] = acc[mt][nt][3];
        }
    }
    __syncthreads();
    for (int idx = tid; idx < O * 64; idx += 256) {
        int o = idx >> 6, tl = idx & 63;
        int t = t0 + tl;
        if (t < Tconv) {
            float v = Dt[tl * DP + o] + bias_sh[o];
            if (RELU) v = fmaxf(v, 0.f);
            size_t oi = ((size_t)b * O + o) * Tconv + t;
            if (OUT_PACKED) ((u32*)yv)[oi] = split1(v);
            else            ((float*)yv)[oi] = v;
        }
    }
}

// ---------------------------------------------------------------------------
// Masked adaptive-max over valid frames + 3-layer MLP head
// ---------------------------------------------------------------------------
__global__ void head_kernel(const float* __restrict__ y7,       // [64][128][14]
                            const int* __restrict__ len_mask,
                            const float* __restrict__ lw1, const float* __restrict__ lb1,
                            const float* __restrict__ lw2, const float* __restrict__ lb2,
                            const float* __restrict__ lw3, const float* __restrict__ lb3,
                            float* __restrict__ out) {
    __shared__ float v[128], h1[128], h2[64];
    const int b = blockIdx.x;
    const int tid = threadIdx.x;

    int L = len_mask[b];
    L = (L - 10) / 2 + 1;
    L = (L - 5) / 2 + 1;
    L = (L - 5) / 2 + 1;
    L = (L - 5) / 2 + 1;
    L >>= 1;
    L = (L - 5) / 2 + 1;
    L >>= 1;
    L = (L - 5) / 2 + 1;
    L = (L - 3) / 2 + 1;
    if (L > 14) L = 14;
    if (L < 1)  L = 1;

    const float* row = y7 + ((size_t)b * 128 + tid) * 14;
    float m = -3.4e38f;
    for (int t = 0; t < L; t++) m = fmaxf(m, row[t]);
    v[tid] = m;
    __syncthreads();

    float s = lb1[tid];
#pragma unroll 8
    for (int i = 0; i < 128; i++) s += lw1[tid * 128 + i] * v[i];
    h1[tid] = fmaxf(s, 0.f);
    __syncthreads();

    if (tid < 64) {
        float s2 = lb2[tid];
#pragma unroll 8
        for (int i = 0; i < 128; i++) s2 += lw2[tid * 128 + i] * h1[i];
        h2[tid] = fmaxf(s2, 0.f);
    }
    __syncthreads();

    if (tid < 5) {
        float s3 = lb3[tid];
#pragma unroll 8
        for (int i = 0; i < 64; i++) s3 += lw3[tid * 64 + i] * h2[i];
        out[b * 5 + tid] = s3;
    }
}

// ---------------------------------------------------------------------------
// Launch
// ---------------------------------------------------------------------------
extern "C" void kernel_launch(void* const* d_in, const int* in_sizes, int n_in,
                              void* d_out, int out_size) {
    const float* x    = (const float*)d_in[0];
    const int*   lenm = (const int*)d_in[1];
    const float* w1 = (const float*)d_in[2];  const float* b1 = (const float*)d_in[3];
    const float* w2 = (const float*)d_in[4];  const float* b2 = (const float*)d_in[5];
    const float* w3 = (const float*)d_in[6];  const float* b3 = (const float*)d_in[7];
    const float* w4 = (const float*)d_in[8];  const float* b4 = (const float*)d_in[9];
    const float* w5 = (const float*)d_in[10]; const float* b5 = (const float*)d_in[11];
    const float* w6 = (const float*)d_in[12]; const float* b6 = (const float*)d_in[13];
    const float* w7 = (const float*)d_in[14]; const float* b7 = (const float*)d_in[15];
    const float* lw1 = (const float*)d_in[16]; const float* lb1 = (const float*)d_in[17];
    const float* lw2 = (const float*)d_in[18]; const float* lb2 = (const float*)d_in[19];
    const float* lw3 = (const float*)d_in[20]; const float* lb3 = (const float*)d_in[21];

    u32* base = nullptr;
    cudaGetSymbolAddress((void**)&base, g_scratch);
    u16* wsp = nullptr;
    cudaGetSymbolAddress((void**)&wsp, g_wsplit);

    u32* B1 = base + OFF_B1;
    u32* B2 = base + OFF_B2;
    u32* B3 = base + OFF_B3;
    u32* B4 = base + OFF_B4;
    u32* B5 = base + OFF_B5;
    u32* B6 = base + OFF_B6;
    float* B7 = (float*)(base + OFF_B7);

    // kernels:                I   O    K  RELU  IN  OUTPK OCC
    auto m1 = conv_hmma_kernel<40, 96, 10, true,  0, true,  3>;  // 67KB -> 3/SM
    auto m2 = conv_hmma_kernel<96, 96,  5, true,  1, true,  2>;  // conv2, conv3
    auto m4 = conv_hmma_kernel<96, 96,  5, false, 1, true,  2>;  // conv4
    auto m5 = conv_hmma_kernel<96, 96,  5, false, 2, true,  2>;  // conv5 (pool in)
    auto m6 = conv_hmma_kernel<96, 96,  5, true,  2, true,  2>;  // conv6 (pool in)
    auto m7 = conv_hmma_kernel<96, 128, 3, true,  1, false, 2>;  // conv7 -> fp32

    const int SM1 = hx_smem(40, 10, 96);
    const int SM2 = hx_smem(96, 5, 96);
    const int SM7 = hx_smem(96, 3, 128);
    cudaFuncSetAttribute(m1, cudaFuncAttributeMaxDynamicSharedMemorySize, SM1);
    cudaFuncSetAttribute(m2, cudaFuncAttributeMaxDynamicSharedMemorySize, SM2);
    cudaFuncSetAttribute(m4, cudaFuncAttributeMaxDynamicSharedMemorySize, SM2);
    cudaFuncSetAttribute(m5, cudaFuncAttributeMaxDynamicSharedMemorySize, SM2);
    cudaFuncSetAttribute(m6, cudaFuncAttributeMaxDynamicSharedMemorySize, SM2);
    cudaFuncSetAttribute(m7, cudaFuncAttributeMaxDynamicSharedMemorySize, SM7);

    // 0: weight pre-split (all 7 conv weights)
    presplit_w_kernel<<<(329728 + 255) / 256, 256>>>(w1, w2, w3, w4, w5, w6, w7);

    // 1-7: HMMA convs (M tile 64)
    m1<<<dim3(64, 64), 256, SM1>>>(x,  wsp + W1H, wsp + W1L, b1, B1, 8192, 8192, 4092);
    m2<<<dim3(32, 64), 256, SM2>>>(B1, wsp + W2H, wsp + W2L, b2, B2, 4092, 4092, 2044);
    m2<<<dim3(16, 64), 256, SM2>>>(B2, wsp + W3H, wsp + W3L, b3, B3, 2044, 2044, 1020);
    m4<<<dim3(8, 64),  256, SM2>>>(B3, wsp + W4H, wsp + W4L, b4, B4, 1020, 1020, 508);
    m5<<<dim3(2, 64),  256, SM2>>>(B4, wsp + W5H, wsp + W5L, b5, B5, 254, 508, 125);
    m6<<<dim3(1, 64),  256, SM2>>>(B5, wsp + W6H, wsp + W6L, b6, B6, 62, 125, 29);
    m7<<<dim3(1, 64),  256, SM7>>>(B6, wsp + W7H, wsp + W7L, b7, B7, 29, 29, 14);

    // 8: masked max + MLP head
    head_kernel<<<64, 128>>>(B7, lenm, lw1, lb1, lw2, lb2, lw3, lb3,
                             (float*)d_out);
}